// round 10
// baseline (speedup 1.0000x reference)
#include <cuda_runtime.h>

#define NN 50000
#define NE 800000
// F_IN=128, F_HID=64, F_OUT=32

// ---------------- scratch (device globals: alloc-free) ----------------
__device__ __align__(16) float g_deg [NN];
__device__ __align__(16) float g_dinv[NN];
__device__ __align__(16) float g_H1  [NN * 64];   // (x@W1) * dinv[node]
__device__ __align__(16) float g_AGG1[NN * 64];
__device__ __align__(16) float g_H2  [NN * 32];   // (h@W2) * dinv[node]
__device__ int g_src[NE];
__device__ int g_dst[NE];
__device__ int g_is64;

// packed f32x2 FMA: d = a*b + d  (lane-wise on a 64-bit register pair)
#define FFMA2(acc, a, b) \
    asm("fma.rn.f32x2 %0, %1, %2, %0;" : "+l"(acc) : "l"(a), "l"(b))

__device__ __forceinline__ float pair_sum(unsigned long long p) {
    union { unsigned long long u; float2 f; } c; c.u = p;
    return c.f.x + c.f.y;
}

// ---------------- init: deg=1 (self-loop) + edge dtype detect ----------------
__global__ void k_init(const unsigned* __restrict__ w) {
    int i = blockIdx.x * 256 + threadIdx.x;
    if (i < NN) g_deg[i] = 1.0f;
    if (blockIdx.x == 0 && threadIdx.x == 0) {
        int all0 = 1;
        for (int k = 0; k < 64; k++)
            if (w[2 * k + 1] != 0u) all0 = 0;
        g_is64 = all0;
    }
}

// decode edge_index to int32 + accumulate degree, 2 edges per thread
__global__ void k_prep(const void* __restrict__ p) {
    int e0 = (blockIdx.x * 256 + threadIdx.x) * 2;
    if (e0 >= NE) return;
#pragma unroll
    for (int u = 0; u < 2; u++) {
        int e = e0 + u;
        if (e >= NE) break;
        int s, d;
        if (g_is64) {
            const long long* q = (const long long*)p;
            s = (int)q[e];  d = (int)q[NE + e];
        } else {
            const int* q = (const int*)p;
            s = q[e];       d = q[NE + e];
        }
        g_src[e] = s;  g_dst[e] = d;
        if ((unsigned)d < NN) atomicAdd(&g_deg[d], 1.0f);
    }
}

// ---------------- GEMM1: H1s = (x @ W1) * dinv ; AGG1 = H1s ; store dinv ----------------
// FFMA2 mainloop: accumulator pairs along k; Wt transposed k-contiguous in smem.
__global__ __launch_bounds__(256, 2) void k_gemm1(const float* __restrict__ x,
                                                  const float* __restrict__ W1) {
    extern __shared__ float smem[];
    float* Wt = smem;               // [64 cols][132]  Wt[c*132+k] = W1[k*64+c]
    float* xs = smem + 64 * 132;    // [128 rows][132]
    const int t = threadIdx.x;
    const int node0 = blockIdx.x * 128;

    for (int i = t; i < 64 * 128; i += 256) {
        int col = i >> 7, k = i & 127;
        Wt[col * 132 + k] = W1[k * 64 + col];
    }
    for (int i = t; i < 128 * 128; i += 256) {
        int row = i >> 7, col = i & 127;
        int node = node0 + row;
        xs[row * 132 + col] = (node < NN) ? x[node * 128 + col] : 0.0f;
    }
    __syncthreads();

    const int ng = t >> 3;   // 4 nodes each
    const int cg = t & 7;    // 8 cols each
    unsigned long long acc2[4][8];
#pragma unroll
    for (int i = 0; i < 4; i++)
#pragma unroll
        for (int j = 0; j < 8; j++) acc2[i][j] = 0ULL;   // (0.0f, 0.0f)

    const float* xp = xs + ng * 4 * 132;
    const float* wp = Wt + cg * 8 * 132;
    for (int k = 0; k < 128; k += 4) {
        ulonglong2 xv[4];
#pragma unroll
        for (int i = 0; i < 4; i++)
            xv[i] = *(const ulonglong2*)(xp + i * 132 + k);
#pragma unroll
        for (int j = 0; j < 8; j++) {
            ulonglong2 wv = *(const ulonglong2*)(wp + j * 132 + k);
#pragma unroll
            for (int i = 0; i < 4; i++) {
                FFMA2(acc2[i][j], xv[i].x, wv.x);
                FFMA2(acc2[i][j], xv[i].y, wv.y);
            }
        }
    }

#pragma unroll
    for (int i = 0; i < 4; i++) {
        int node = node0 + ng * 4 + i;
        if (node < NN) {
            float s = rsqrtf(g_deg[node]);
            g_dinv[node] = s;
            float v[8];
#pragma unroll
            for (int j = 0; j < 8; j++) v[j] = pair_sum(acc2[i][j]) * s;
            float4 v0 = make_float4(v[0], v[1], v[2], v[3]);
            float4 v1 = make_float4(v[4], v[5], v[6], v[7]);
            ((float4*)(g_H1   + node * 64 + cg * 8))[0] = v0;
            ((float4*)(g_H1   + node * 64 + cg * 8))[1] = v1;
            ((float4*)(g_AGG1 + node * 64 + cg * 8))[0] = v0;
            ((float4*)(g_AGG1 + node * 64 + cg * 8))[1] = v1;
        }
    }
}

// ---------------- scatter layer 1: AGG1[dst] += H1s[src], 2 edges per thread ----------------
__global__ void k_scatter1() {
    int i = blockIdx.x * 256 + threadIdx.x;
    if (i >= NE * 8) return;             // NE/2 edge-pairs x 16 threads
    int e0 = (i >> 4) * 2, c = i & 15;
    unsigned s0 = (unsigned)g_src[e0],     d0 = (unsigned)g_dst[e0];
    unsigned s1 = (unsigned)g_src[e0 + 1], d1 = (unsigned)g_dst[e0 + 1];
    bool ok0 = (s0 < NN) & (d0 < NN);
    bool ok1 = (s1 < NN) & (d1 < NN);
    float4 v0, v1;
    if (ok0) v0 = ((const float4*)g_H1)[s0 * 16 + c];
    if (ok1) v1 = ((const float4*)g_H1)[s1 * 16 + c];
    if (ok0) atomicAdd(((float4*)g_AGG1) + d0 * 16 + c, v0);
    if (ok1) atomicAdd(((float4*)g_AGG1) + d1 * 16 + c, v1);
}

// ---------------- GEMM2: h = relu(dinv*AGG1 + b1); H2s = (h@W2)*dinv ; out init = H2s ----------------
__global__ __launch_bounds__(256) void k_gemm2(const float* __restrict__ W2,
                                               const float* __restrict__ b1,
                                               float* __restrict__ out) {
    __shared__ float Wt[32 * 68];    // Wt[c*68+k] = W2[k*32+c]
    __shared__ float hs[128 * 68];
    const int t = threadIdx.x;
    const int node0 = blockIdx.x * 128;

    for (int i = t; i < 32 * 64; i += 256) {
        int col = i >> 6, k = i & 63;
        Wt[col * 68 + k] = W2[k * 32 + col];
    }
    for (int i = t; i < 128 * 64; i += 256) {
        int row = i >> 6, col = i & 63;
        int node = node0 + row;
        float h = 0.0f;
        if (node < NN) h = fmaxf(fmaf(g_dinv[node], g_AGG1[node * 64 + col], b1[col]), 0.0f);
        hs[row * 68 + col] = h;
    }
    __syncthreads();

    const int ng = t >> 3;   // 4 nodes
    const int cg = t & 7;    // 4 cols each
    unsigned long long acc2[4][4];
#pragma unroll
    for (int i = 0; i < 4; i++)
#pragma unroll
        for (int j = 0; j < 4; j++) acc2[i][j] = 0ULL;

    const float* hp = hs + ng * 4 * 68;
    const float* wp = Wt + cg * 4 * 68;
    for (int k = 0; k < 64; k += 4) {
        ulonglong2 xv[4];
#pragma unroll
        for (int i = 0; i < 4; i++)
            xv[i] = *(const ulonglong2*)(hp + i * 68 + k);
#pragma unroll
        for (int j = 0; j < 4; j++) {
            ulonglong2 wv = *(const ulonglong2*)(wp + j * 68 + k);
#pragma unroll
            for (int i = 0; i < 4; i++) {
                FFMA2(acc2[i][j], xv[i].x, wv.x);
                FFMA2(acc2[i][j], xv[i].y, wv.y);
            }
        }
    }

#pragma unroll
    for (int i = 0; i < 4; i++) {
        int node = node0 + ng * 4 + i;
        if (node < NN) {
            float s = g_dinv[node];
            float4 h2 = make_float4(pair_sum(acc2[i][0]) * s, pair_sum(acc2[i][1]) * s,
                                    pair_sum(acc2[i][2]) * s, pair_sum(acc2[i][3]) * s);
            ((float4*)(g_H2 + node * 32 + cg * 4))[0] = h2;
            ((float4*)(out  + node * 32 + cg * 4))[0] = h2;
        }
    }
}

// ---------------- scatter layer 2: out[dst] += H2s[src], 2 edges per thread ----------------
__global__ void k_scatter2(float* __restrict__ out) {
    int i = blockIdx.x * 256 + threadIdx.x;
    if (i >= NE * 4) return;             // NE/2 edge-pairs x 8 threads
    int e0 = (i >> 3) * 2, c = i & 7;
    unsigned s0 = (unsigned)g_src[e0],     d0 = (unsigned)g_dst[e0];
    unsigned s1 = (unsigned)g_src[e0 + 1], d1 = (unsigned)g_dst[e0 + 1];
    bool ok0 = (s0 < NN) & (d0 < NN);
    bool ok1 = (s1 < NN) & (d1 < NN);
    float4 v0, v1;
    if (ok0) v0 = ((const float4*)g_H2)[s0 * 8 + c];
    if (ok1) v1 = ((const float4*)g_H2)[s1 * 8 + c];
    if (ok0) atomicAdd(((float4*)out) + d0 * 8 + c, v0);
    if (ok1) atomicAdd(((float4*)out) + d1 * 8 + c, v1);
}

// ---------------- final: out = out * dinv[node] + b2 ----------------
__global__ void k_final(float* __restrict__ out, const float* __restrict__ b2) {
    int i = blockIdx.x * 256 + threadIdx.x;
    if (i >= NN * 8) return;
    int node = i >> 3, cb = (i & 7) * 4;
    float s = g_dinv[node];
    float4 v = ((float4*)out)[i];
    float4 bb = *(const float4*)(b2 + cb);
    ((float4*)out)[i] = make_float4(fmaf(v.x, s, bb.x), fmaf(v.y, s, bb.y),
                                    fmaf(v.z, s, bb.z), fmaf(v.w, s, bb.w));
}

// ---------------- launch ----------------
extern "C" void kernel_launch(void* const* d_in, const int* in_sizes, int n_in,
                              void* d_out, int out_size) {
    const float* x  = (const float*)d_in[0];
    const void*  ei = d_in[1];
    const float* W1 = (const float*)d_in[2];
    const float* b1 = (const float*)d_in[3];
    const float* W2 = (const float*)d_in[4];
    const float* b2 = (const float*)d_in[5];
    float* out = (float*)d_out;

    const int smem1 = (64 * 132 + 128 * 132) * sizeof(float);  // 101376 B
    cudaFuncSetAttribute(k_gemm1, cudaFuncAttributeMaxDynamicSharedMemorySize, smem1);

    k_init    <<<(NN + 255) / 256, 256>>>((const unsigned*)ei);
    k_prep    <<<(NE / 2 + 255) / 256, 256>>>(ei);
    k_gemm1   <<<(NN + 127) / 128, 256, smem1>>>(x, W1);
    k_scatter1<<<(NE * 8 + 255) / 256, 256>>>();
    k_gemm2   <<<(NN + 127) / 128, 256>>>(W2, b1, out);
    k_scatter2<<<(NE * 4 + 255) / 256, 256>>>(out);
    k_final   <<<(NN * 8 + 255) / 256, 256>>>(out, b2);
}

// round 11
// speedup vs baseline: 1.7359x; 1.7359x over previous
#include <cuda_runtime.h>

#define NN 50000
#define NE 800000
// F_IN=128, F_HID=64, F_OUT=32

// ---------------- scratch (device globals: alloc-free) ----------------
__device__ __align__(16) float g_deg [NN];
__device__ __align__(16) float g_dinv[NN];
__device__ __align__(16) float g_H1  [NN * 64];   // (x@W1) * dinv[node]  (pre-scaled)
__device__ __align__(16) float g_AGG1[NN * 64];
__device__ __align__(16) float g_H2  [NN * 32];   // (h@W2) * dinv[node]  (pre-scaled)
__device__ int g_src[NE];
__device__ int g_dst[NE];
__device__ int g_is64;

// ---------------- init: deg=1 (self-loop) + edge dtype detect ----------------
// int64 indices < 50000 => every odd 32-bit word is 0. Probe is in-bounds for both layouts.
__global__ void k_init(const unsigned* __restrict__ w) {
    int i = blockIdx.x * 256 + threadIdx.x;
    if (i < NN) g_deg[i] = 1.0f;
    if (blockIdx.x == 0 && threadIdx.x == 0) {
        int all0 = 1;
        for (int k = 0; k < 64; k++)
            if (w[2 * k + 1] != 0u) all0 = 0;
        g_is64 = all0;
    }
}

// decode edge_index to int32 + accumulate degree, 2 edges per thread
__global__ void k_prep(const void* __restrict__ p) {
    int e0 = (blockIdx.x * 256 + threadIdx.x) * 2;
    if (e0 >= NE) return;
#pragma unroll
    for (int u = 0; u < 2; u++) {
        int e = e0 + u;
        if (e >= NE) break;
        int s, d;
        if (g_is64) {
            const long long* q = (const long long*)p;
            s = (int)q[e];  d = (int)q[NE + e];
        } else {
            const int* q = (const int*)p;
            s = q[e];       d = q[NE + e];
        }
        g_src[e] = s;  g_dst[e] = d;
        if ((unsigned)d < NN) atomicAdd(&g_deg[d], 1.0f);
    }
}

// ---------------- GEMM1: H1s = (x @ W1) * dinv ; AGG1 = H1s (self-loop init) ; store dinv ----------------
__global__ __launch_bounds__(256) void k_gemm1(const float* __restrict__ x,
                                               const float* __restrict__ W1) {
    extern __shared__ float smem[];
    float* Ws = smem;              // 128*64
    float* xs = smem + 128 * 64;   // 128*130 (pad 2)
    const int t = threadIdx.x;
    const int node0 = blockIdx.x * 128;

    for (int i = t; i < 128 * 64 / 4; i += 256)
        ((float4*)Ws)[i] = ((const float4*)W1)[i];
    for (int i = t; i < 128 * 128; i += 256) {
        int row = i >> 7, col = i & 127;
        int node = node0 + row;
        xs[row * 130 + col] = (node < NN) ? x[node * 128 + col] : 0.0f;
    }
    __syncthreads();

    const int ng = t >> 3;   // 4 nodes each
    const int cg = t & 7;    // 8 cols each
    float acc[4][8];
#pragma unroll
    for (int i = 0; i < 4; i++)
#pragma unroll
        for (int j = 0; j < 8; j++) acc[i][j] = 0.0f;

    const float* xp = xs + ng * 4 * 130;
    const float* wp = Ws + cg * 8;
#pragma unroll 2
    for (int k = 0; k < 128; k++) {
        float4 w0 = *(const float4*)(wp + k * 64);
        float4 w1 = *(const float4*)(wp + k * 64 + 4);
        float xv[4];
#pragma unroll
        for (int i = 0; i < 4; i++) xv[i] = xp[i * 130 + k];
#pragma unroll
        for (int i = 0; i < 4; i++) {
            acc[i][0] += xv[i] * w0.x; acc[i][1] += xv[i] * w0.y;
            acc[i][2] += xv[i] * w0.z; acc[i][3] += xv[i] * w0.w;
            acc[i][4] += xv[i] * w1.x; acc[i][5] += xv[i] * w1.y;
            acc[i][6] += xv[i] * w1.z; acc[i][7] += xv[i] * w1.w;
        }
    }

#pragma unroll
    for (int i = 0; i < 4; i++) {
        int node = node0 + ng * 4 + i;
        if (node < NN) {
            float s = rsqrtf(g_deg[node]);
            g_dinv[node] = s;
            float4 v0 = make_float4(acc[i][0]*s, acc[i][1]*s, acc[i][2]*s, acc[i][3]*s);
            float4 v1 = make_float4(acc[i][4]*s, acc[i][5]*s, acc[i][6]*s, acc[i][7]*s);
            ((float4*)(g_H1   + node * 64 + cg * 8))[0] = v0;
            ((float4*)(g_H1   + node * 64 + cg * 8))[1] = v1;
            ((float4*)(g_AGG1 + node * 64 + cg * 8))[0] = v0;
            ((float4*)(g_AGG1 + node * 64 + cg * 8))[1] = v1;
        }
    }
}

// ---------------- scatter layer 1: AGG1[dst] += H1s[src], 4 edges per thread ----------------
__global__ void k_scatter1() {
    int i = blockIdx.x * 256 + threadIdx.x;
    if (i >= NE * 4) return;             // NE/4 edge-quads x 16 threads
    int e0 = (i >> 4) * 4, c = i & 15;
    unsigned s[4], d[4];
    bool ok[4];
#pragma unroll
    for (int u = 0; u < 4; u++) {
        s[u] = (unsigned)g_src[e0 + u];
        d[u] = (unsigned)g_dst[e0 + u];
        ok[u] = (s[u] < NN) & (d[u] < NN);
    }
    float4 v[4];
#pragma unroll
    for (int u = 0; u < 4; u++)
        if (ok[u]) v[u] = ((const float4*)g_H1)[s[u] * 16 + c];
#pragma unroll
    for (int u = 0; u < 4; u++)
        if (ok[u]) atomicAdd(((float4*)g_AGG1) + d[u] * 16 + c, v[u]);
}

// ---------------- GEMM2: h = relu(dinv*AGG1 + b1); H2s = (h@W2)*dinv ; out init = H2s ----------------
__global__ __launch_bounds__(256) void k_gemm2(const float* __restrict__ W2,
                                               const float* __restrict__ b1,
                                               float* __restrict__ out) {
    __shared__ float Ws[64 * 32];
    __shared__ float hs[128 * 66];   // pad 2
    const int t = threadIdx.x;
    const int node0 = blockIdx.x * 128;

    for (int i = t; i < 64 * 32; i += 256) Ws[i] = W2[i];
    for (int i = t; i < 128 * 64; i += 256) {
        int row = i >> 6, col = i & 63;
        int node = node0 + row;
        float h = 0.0f;
        if (node < NN) h = fmaxf(fmaf(g_dinv[node], g_AGG1[node * 64 + col], b1[col]), 0.0f);
        hs[row * 66 + col] = h;
    }
    __syncthreads();

    const int ng = t >> 3;   // 4 nodes
    const int cg = t & 7;    // 4 cols
    float acc[4][4];
#pragma unroll
    for (int i = 0; i < 4; i++)
#pragma unroll
        for (int j = 0; j < 4; j++) acc[i][j] = 0.0f;

    const float* hp = hs + ng * 4 * 66;
    const float* wp = Ws + cg * 4;
#pragma unroll 4
    for (int k = 0; k < 64; k++) {
        float4 w = *(const float4*)(wp + k * 32);
        float hv[4];
#pragma unroll
        for (int i = 0; i < 4; i++) hv[i] = hp[i * 66 + k];
#pragma unroll
        for (int i = 0; i < 4; i++) {
            acc[i][0] += hv[i] * w.x; acc[i][1] += hv[i] * w.y;
            acc[i][2] += hv[i] * w.z; acc[i][3] += hv[i] * w.w;
        }
    }

#pragma unroll
    for (int i = 0; i < 4; i++) {
        int node = node0 + ng * 4 + i;
        if (node < NN) {
            float s = g_dinv[node];
            float4 h2 = make_float4(acc[i][0]*s, acc[i][1]*s, acc[i][2]*s, acc[i][3]*s);
            ((float4*)(g_H2 + node * 32 + cg * 4))[0] = h2;
            ((float4*)(out  + node * 32 + cg * 4))[0] = h2;
        }
    }
}

// ---------------- scatter layer 2: out[dst] += H2s[src], 4 edges per thread ----------------
__global__ void k_scatter2(float* __restrict__ out) {
    int i = blockIdx.x * 256 + threadIdx.x;
    if (i >= NE * 2) return;             // NE/4 edge-quads x 8 threads
    int e0 = (i >> 3) * 4, c = i & 7;
    unsigned s[4], d[4];
    bool ok[4];
#pragma unroll
    for (int u = 0; u < 4; u++) {
        s[u] = (unsigned)g_src[e0 + u];
        d[u] = (unsigned)g_dst[e0 + u];
        ok[u] = (s[u] < NN) & (d[u] < NN);
    }
    float4 v[4];
#pragma unroll
    for (int u = 0; u < 4; u++)
        if (ok[u]) v[u] = ((const float4*)g_H2)[s[u] * 8 + c];
#pragma unroll
    for (int u = 0; u < 4; u++)
        if (ok[u]) atomicAdd(((float4*)out) + d[u] * 8 + c, v[u]);
}

// ---------------- final: out = out * dinv[node] + b2 ----------------
__global__ void k_final(float* __restrict__ out, const float* __restrict__ b2) {
    int i = blockIdx.x * 256 + threadIdx.x;
    if (i >= NN * 8) return;
    int node = i >> 3, cb = (i & 7) * 4;
    float s = g_dinv[node];
    float4 v = ((float4*)out)[i];
    float4 bb = *(const float4*)(b2 + cb);
    ((float4*)out)[i] = make_float4(fmaf(v.x, s, bb.x), fmaf(v.y, s, bb.y),
                                    fmaf(v.z, s, bb.z), fmaf(v.w, s, bb.w));
}

// ---------------- launch ----------------
extern "C" void kernel_launch(void* const* d_in, const int* in_sizes, int n_in,
                              void* d_out, int out_size) {
    const float* x  = (const float*)d_in[0];
    const void*  ei = d_in[1];
    const float* W1 = (const float*)d_in[2];
    const float* b1 = (const float*)d_in[3];
    const float* W2 = (const float*)d_in[4];
    const float* b2 = (const float*)d_in[5];
    float* out = (float*)d_out;

    const int smem1 = (128 * 64 + 128 * 130) * sizeof(float);  // 99328 B
    cudaFuncSetAttribute(k_gemm1, cudaFuncAttributeMaxDynamicSharedMemorySize, smem1);

    k_init    <<<(NN + 255) / 256, 256>>>((const unsigned*)ei);
    k_prep    <<<(NE / 2 + 255) / 256, 256>>>(ei);
    k_gemm1   <<<(NN + 127) / 128, 256, smem1>>>(x, W1);
    k_scatter1<<<(NE * 4 + 255) / 256, 256>>>();
    k_gemm2   <<<(NN + 127) / 128, 256>>>(W2, b1, out);
    k_scatter2<<<(NE * 2 + 255) / 256, 256>>>(out);
    k_final   <<<(NN * 8 + 255) / 256, 256>>>(out, b2);
}

// round 13
// speedup vs baseline: 1.7394x; 1.0020x over previous
#include <cuda_runtime.h>
#include <cstdint>

#define NN 50000
#define NE 800000
// F_IN=128, F_HID=64, F_OUT=32

// ---------------- scratch (device globals: alloc-free) ----------------
__device__ __align__(16) float g_deg [NN];
__device__ __align__(16) float g_dinv[NN];
__device__ __align__(16) float g_H1  [NN * 64];   // (x@W1) * dinv[node]
__device__ __align__(16) float g_AGG1[NN * 64];
__device__ __align__(16) float g_H2  [NN * 32];   // (h@W2) * dinv[node]
__device__ int g_src[NE];
__device__ int g_dst[NE];
__device__ int g_is64;

__device__ __forceinline__ uint32_t f2tf32(float v) {
    uint32_t r;
    asm("cvt.rna.tf32.f32 %0, %1;" : "=r"(r) : "f"(v));
    return r;
}

#define MMA_TF32(d0,d1,d2,d3,a0,a1,a2,a3,b0,b1) \
    asm volatile("mma.sync.aligned.m16n8k8.row.col.f32.tf32.tf32.f32 " \
                 "{%0,%1,%2,%3}, {%4,%5,%6,%7}, {%8,%9}, {%0,%1,%2,%3};" \
                 : "+f"(d0), "+f"(d1), "+f"(d2), "+f"(d3) \
                 : "r"(a0), "r"(a1), "r"(a2), "r"(a3), "r"(b0), "r"(b1))

// ---------------- init: deg=1 (self-loop) + edge dtype detect ----------------
__global__ void k_init(const unsigned* __restrict__ w) {
    int i = blockIdx.x * 256 + threadIdx.x;
    if (i < NN) g_deg[i] = 1.0f;
    if (blockIdx.x == 0 && threadIdx.x == 0) {
        int all0 = 1;
        for (int k = 0; k < 64; k++)
            if (w[2 * k + 1] != 0u) all0 = 0;
        g_is64 = all0;
    }
}

// decode edge_index to int32 + accumulate degree, 2 edges per thread
__global__ void k_prep(const void* __restrict__ p) {
    int e0 = (blockIdx.x * 256 + threadIdx.x) * 2;
    if (e0 >= NE) return;
#pragma unroll
    for (int u = 0; u < 2; u++) {
        int e = e0 + u;
        if (e >= NE) break;
        int s, d;
        if (g_is64) {
            const long long* q = (const long long*)p;
            s = (int)q[e];  d = (int)q[NE + e];
        } else {
            const int* q = (const int*)p;
            s = q[e];       d = q[NE + e];
        }
        g_src[e] = s;  g_dst[e] = d;
        if ((unsigned)d < NN) atomicAdd(&g_deg[d], 1.0f);
    }
}

// ---------------- GEMM1 (mma.sync tf32, 3xTF32): H1s = (x @ W1) * dinv ; AGG1 = H1s ----------------
// 256 threads = 8 warps; warp owns 16 rows x 64 cols (8 n-tiles of m16n8k8), K=128 in 16 steps.
__global__ __launch_bounds__(256) void k_gemm1_mma(const float* __restrict__ x,
                                                   const float* __restrict__ W1) {
    extern __shared__ float sm[];
    float* Wh = sm;                   // [128][68] tf32-hi of W1^T-access pattern (k-major)
    float* Wl = sm + 128 * 68;        // [128][68] tf32-lo
    float* xs = sm + 2 * 128 * 68;    // [128][132] fp32 x tile
    const int t = threadIdx.x, wid = t >> 5, lane = t & 31;
    const int gid = lane >> 2, tig = lane & 3;   // groupID, threadID-in-group
    const int node0 = blockIdx.x * 128;

    // stage W1 (128x64 row-major), split hi/lo
    for (int i = t; i < 128 * 64; i += 256) {
        int k = i >> 6, n = i & 63;
        float w = W1[i];
        uint32_t hb = f2tf32(w);
        float hf = __uint_as_float(hb);
        Wh[k * 68 + n] = hf;
        Wl[k * 68 + n] = __uint_as_float(f2tf32(w - hf));
    }
    // stage x tile (float4)
    for (int i4 = t; i4 < 128 * 32; i4 += 256) {
        int row = i4 >> 5, q = i4 & 31;
        int node = node0 + row;
        float4 v = make_float4(0.f, 0.f, 0.f, 0.f);
        if (node < NN) v = ((const float4*)(x + (size_t)node * 128))[q];
        *(float4*)(xs + row * 132 + q * 4) = v;
    }
    __syncthreads();

    float acc[8][4];
#pragma unroll
    for (int j = 0; j < 8; j++)
#pragma unroll
        for (int c = 0; c < 4; c++) acc[j][c] = 0.0f;

    const float* xr0 = xs + (wid * 16 + gid) * 132;      // row gid
    const float* xr1 = xr0 + 8 * 132;                    // row gid+8
    for (int kk = 0; kk < 128; kk += 8) {
        // A fragment (m16k8): a0..a3, split hi/lo in regs
        float a0 = xr0[kk + tig],     a1 = xr1[kk + tig];
        float a2 = xr0[kk + tig + 4], a3 = xr1[kk + tig + 4];
        uint32_t ah0 = f2tf32(a0), ah1 = f2tf32(a1), ah2 = f2tf32(a2), ah3 = f2tf32(a3);
        uint32_t al0 = f2tf32(a0 - __uint_as_float(ah0));
        uint32_t al1 = f2tf32(a1 - __uint_as_float(ah1));
        uint32_t al2 = f2tf32(a2 - __uint_as_float(ah2));
        uint32_t al3 = f2tf32(a3 - __uint_as_float(ah3));
        const float* wh0 = Wh + (kk + tig) * 68;
        const float* wh1 = Wh + (kk + tig + 4) * 68;
        const float* wl0 = Wl + (kk + tig) * 68;
        const float* wl1 = Wl + (kk + tig + 4) * 68;
#pragma unroll
        for (int j = 0; j < 8; j++) {
            int n = j * 8 + gid;
            uint32_t bh0 = __float_as_uint(wh0[n]);
            uint32_t bh1 = __float_as_uint(wh1[n]);
            uint32_t bl0 = __float_as_uint(wl0[n]);
            uint32_t bl1 = __float_as_uint(wl1[n]);
            MMA_TF32(acc[j][0], acc[j][1], acc[j][2], acc[j][3],
                     ah0, ah1, ah2, ah3, bh0, bh1);
            MMA_TF32(acc[j][0], acc[j][1], acc[j][2], acc[j][3],
                     al0, al1, al2, al3, bh0, bh1);
            MMA_TF32(acc[j][0], acc[j][1], acc[j][2], acc[j][3],
                     ah0, ah1, ah2, ah3, bl0, bl1);
        }
    }

    // epilogue: thread holds rows (wid*16+gid) and +8, cols j*8 + tig*2 (+1)
    int row0 = node0 + wid * 16 + gid;
    int row1 = row0 + 8;
    float s0 = 0.f, s1 = 0.f;
    if (row0 < NN) { s0 = rsqrtf(g_deg[row0]); if (tig == 0) g_dinv[row0] = s0; }
    if (row1 < NN) { s1 = rsqrtf(g_deg[row1]); if (tig == 0) g_dinv[row1] = s1; }
#pragma unroll
    for (int j = 0; j < 8; j++) {
        int col = j * 8 + tig * 2;
        if (row0 < NN) {
            float2 v = make_float2(acc[j][0] * s0, acc[j][1] * s0);
            *(float2*)(g_H1   + (size_t)row0 * 64 + col) = v;
            *(float2*)(g_AGG1 + (size_t)row0 * 64 + col) = v;
        }
        if (row1 < NN) {
            float2 v = make_float2(acc[j][2] * s1, acc[j][3] * s1);
            *(float2*)(g_H1   + (size_t)row1 * 64 + col) = v;
            *(float2*)(g_AGG1 + (size_t)row1 * 64 + col) = v;
        }
    }
}

// ---------------- scatter layer 1: AGG1[dst] += H1s[src], 4 edges per thread ----------------
__global__ void k_scatter1() {
    int i = blockIdx.x * 256 + threadIdx.x;
    if (i >= NE * 4) return;             // NE/4 edge-quads x 16 threads
    int e0 = (i >> 4) * 4, c = i & 15;
    unsigned s[4], d[4];
    bool ok[4];
#pragma unroll
    for (int u = 0; u < 4; u++) {
        s[u] = (unsigned)g_src[e0 + u];
        d[u] = (unsigned)g_dst[e0 + u];
        ok[u] = (s[u] < NN) & (d[u] < NN);
    }
    float4 v[4];
#pragma unroll
    for (int u = 0; u < 4; u++)
        if (ok[u]) v[u] = ((const float4*)g_H1)[s[u] * 16 + c];
#pragma unroll
    for (int u = 0; u < 4; u++)
        if (ok[u]) atomicAdd(((float4*)g_AGG1) + d[u] * 16 + c, v[u]);
}

// ---------------- GEMM2: h = relu(dinv*AGG1 + b1); H2s = (h@W2)*dinv ; out init = H2s ----------------
__global__ __launch_bounds__(256) void k_gemm2(const float* __restrict__ W2,
                                               const float* __restrict__ b1,
                                               float* __restrict__ out) {
    __shared__ float Ws[64 * 32];
    __shared__ float hs[128 * 66];   // pad 2
    const int t = threadIdx.x;
    const int node0 = blockIdx.x * 128;

    for (int i = t; i < 64 * 32; i += 256) Ws[i] = W2[i];
    for (int i = t; i < 128 * 64; i += 256) {
        int row = i >> 6, col = i & 63;
        int node = node0 + row;
        float h = 0.0f;
        if (node < NN) h = fmaxf(fmaf(g_dinv[node], g_AGG1[node * 64 + col], b1[col]), 0.0f);
        hs[row * 66 + col] = h;
    }
    __syncthreads();

    const int ng = t >> 3;   // 4 nodes
    const int cg = t & 7;    // 4 cols
    float acc[4][4];
#pragma unroll
    for (int i = 0; i < 4; i++)
#pragma unroll
        for (int j = 0; j < 4; j++) acc[i][j] = 0.0f;

    const float* hp = hs + ng * 4 * 66;
    const float* wp = Ws + cg * 4;
#pragma unroll 4
    for (int k = 0; k < 64; k++) {
        float4 w = *(const float4*)(wp + k * 32);
        float hv[4];
#pragma unroll
        for (int i = 0; i < 4; i++) hv[i] = hp[i * 66 + k];
#pragma unroll
        for (int i = 0; i < 4; i++) {
            acc[i][0] += hv[i] * w.x; acc[i][1] += hv[i] * w.y;
            acc[i][2] += hv[i] * w.z; acc[i][3] += hv[i] * w.w;
        }
    }

#pragma unroll
    for (int i = 0; i < 4; i++) {
        int node = node0 + ng * 4 + i;
        if (node < NN) {
            float s = g_dinv[node];
            float4 h2 = make_float4(acc[i][0]*s, acc[i][1]*s, acc[i][2]*s, acc[i][3]*s);
            ((float4*)(g_H2 + node * 32 + cg * 4))[0] = h2;
            ((float4*)(out  + node * 32 + cg * 4))[0] = h2;
        }
    }
}

// ---------------- scatter layer 2: out[dst] += H2s[src], 4 edges per thread ----------------
__global__ void k_scatter2(float* __restrict__ out) {
    int i = blockIdx.x * 256 + threadIdx.x;
    if (i >= NE * 2) return;             // NE/4 edge-quads x 8 threads
    int e0 = (i >> 3) * 4, c = i & 7;
    unsigned s[4], d[4];
    bool ok[4];
#pragma unroll
    for (int u = 0; u < 4; u++) {
        s[u] = (unsigned)g_src[e0 + u];
        d[u] = (unsigned)g_dst[e0 + u];
        ok[u] = (s[u] < NN) & (d[u] < NN);
    }
    float4 v[4];
#pragma unroll
    for (int u = 0; u < 4; u++)
        if (ok[u]) v[u] = ((const float4*)g_H2)[s[u] * 8 + c];
#pragma unroll
    for (int u = 0; u < 4; u++)
        if (ok[u]) atomicAdd(((float4*)out) + d[u] * 8 + c, v[u]);
}

// ---------------- final: out = out * dinv[node] + b2 ----------------
__global__ void k_final(float* __restrict__ out, const float* __restrict__ b2) {
    int i = blockIdx.x * 256 + threadIdx.x;
    if (i >= NN * 8) return;
    int node = i >> 3, cb = (i & 7) * 4;
    float s = g_dinv[node];
    float4 v = ((float4*)out)[i];
    float4 bb = *(const float4*)(b2 + cb);
    ((float4*)out)[i] = make_float4(fmaf(v.x, s, bb.x), fmaf(v.y, s, bb.y),
                                    fmaf(v.z, s, bb.z), fmaf(v.w, s, bb.w));
}

// ---------------- launch ----------------
extern "C" void kernel_launch(void* const* d_in, const int* in_sizes, int n_in,
                              void* d_out, int out_size) {
    const float* x  = (const float*)d_in[0];
    const void*  ei = d_in[1];
    const float* W1 = (const float*)d_in[2];
    const float* b1 = (const float*)d_in[3];
    const float* W2 = (const float*)d_in[4];
    const float* b2 = (const float*)d_in[5];
    float* out = (float*)d_out;

    const int smem1 = (2 * 128 * 68 + 128 * 132) * sizeof(float);  // 137216 B
    cudaFuncSetAttribute(k_gemm1_mma, cudaFuncAttributeMaxDynamicSharedMemorySize, smem1);

    k_init     <<<(NN + 255) / 256, 256>>>((const unsigned*)ei);
    k_prep     <<<(NE / 2 + 255) / 256, 256>>>(ei);
    k_gemm1_mma<<<(NN + 127) / 128, 256, smem1>>>(x, W1);
    k_scatter1 <<<(NE * 4 + 255) / 256, 256>>>();
    k_gemm2    <<<(NN + 127) / 128, 256>>>(W2, b1, out);
    k_scatter2 <<<(NE * 2 + 255) / 256, 256>>>(out);
    k_final    <<<(NN * 8 + 255) / 256, 256>>>(out, b2);
}

// round 14
// speedup vs baseline: 1.7760x; 1.0210x over previous
#include <cuda_runtime.h>
#include <cstdint>

#define NN 50000
#define NE 800000
// F_IN=128, F_HID=64, F_OUT=32

// ---------------- scratch (device globals: alloc-free) ----------------
__device__ __align__(16) float g_deg [NN];
__device__ __align__(16) float g_dinv[NN];
__device__ __align__(16) float g_H1  [NN * 64];   // (x@W1) * dinv[node]
__device__ __align__(16) float g_AGG1[NN * 64];
__device__ __align__(16) float g_H2  [NN * 32];   // (h@W2) * dinv[node]
__device__ int g_src[NE];
__device__ int g_dst[NE];
__device__ int g_is64;

__device__ __forceinline__ uint32_t f2tf32(float v) {
    uint32_t r;
    asm("cvt.rna.tf32.f32 %0, %1;" : "=r"(r) : "f"(v));
    return r;
}

#define MMA_TF32(d0,d1,d2,d3,a0,a1,a2,a3,b0,b1) \
    asm volatile("mma.sync.aligned.m16n8k8.row.col.f32.tf32.tf32.f32 " \
                 "{%0,%1,%2,%3}, {%4,%5,%6,%7}, {%8,%9}, {%0,%1,%2,%3};" \
                 : "+f"(d0), "+f"(d1), "+f"(d2), "+f"(d3) \
                 : "r"(a0), "r"(a1), "r"(a2), "r"(a3), "r"(b0), "r"(b1))

// ---------------- init: deg=1 (self-loop) + edge dtype detect ----------------
__global__ void k_init(const unsigned* __restrict__ w) {
    int i = blockIdx.x * 256 + threadIdx.x;
    if (i < NN) g_deg[i] = 1.0f;
    if (blockIdx.x == 0 && threadIdx.x == 0) {
        int all0 = 1;
        for (int k = 0; k < 64; k++)
            if (w[2 * k + 1] != 0u) all0 = 0;
        g_is64 = all0;
    }
}

// decode edge_index to int32 + accumulate degree, 4 edges per thread
__global__ void k_prep(const void* __restrict__ p) {
    int e0 = (blockIdx.x * 256 + threadIdx.x) * 4;
    if (e0 >= NE) return;
    int s[4], d[4];
    if (g_is64) {
        const long long* q = (const long long*)p;
#pragma unroll
        for (int u = 0; u < 4; u++) {
            s[u] = (int)__ldg(q + e0 + u);
            d[u] = (int)__ldg(q + NE + e0 + u);
        }
    } else {
        const int* q = (const int*)p;
#pragma unroll
        for (int u = 0; u < 4; u++) {
            s[u] = __ldg(q + e0 + u);
            d[u] = __ldg(q + NE + e0 + u);
        }
    }
#pragma unroll
    for (int u = 0; u < 4; u++) { g_src[e0 + u] = s[u]; g_dst[e0 + u] = d[u]; }
#pragma unroll
    for (int u = 0; u < 4; u++)
        if ((unsigned)d[u] < NN) atomicAdd(&g_deg[d[u]], 1.0f);
}

// ---------------- GEMM1 (mma.sync tf32, 3xTF32): H1s = (x @ W1) * dinv ; AGG1 = H1s ----------------
// 256 threads = 8 warps; warp owns 16 rows x 64 cols (8 n-tiles of m16n8k8), K=128 in 16 steps.
__global__ __launch_bounds__(256) void k_gemm1_mma(const float* __restrict__ x,
                                                   const float* __restrict__ W1) {
    extern __shared__ float sm[];
    float* Wh = sm;                   // [128][68] tf32-hi (k-major)
    float* Wl = sm + 128 * 68;        // [128][68] tf32-lo
    float* xs = sm + 2 * 128 * 68;    // [128][132] fp32 x tile
    const int t = threadIdx.x, wid = t >> 5, lane = t & 31;
    const int gid = lane >> 2, tig = lane & 3;   // groupID, threadID-in-group
    const int node0 = blockIdx.x * 128;

    for (int i = t; i < 128 * 64; i += 256) {
        int k = i >> 6, n = i & 63;
        float w = W1[i];
        uint32_t hb = f2tf32(w);
        float hf = __uint_as_float(hb);
        Wh[k * 68 + n] = hf;
        Wl[k * 68 + n] = __uint_as_float(f2tf32(w - hf));
    }
    for (int i4 = t; i4 < 128 * 32; i4 += 256) {
        int row = i4 >> 5, q = i4 & 31;
        int node = node0 + row;
        float4 v = make_float4(0.f, 0.f, 0.f, 0.f);
        if (node < NN) v = ((const float4*)(x + (size_t)node * 128))[q];
        *(float4*)(xs + row * 132 + q * 4) = v;
    }
    __syncthreads();

    float acc[8][4];
#pragma unroll
    for (int j = 0; j < 8; j++)
#pragma unroll
        for (int c = 0; c < 4; c++) acc[j][c] = 0.0f;

    const float* xr0 = xs + (wid * 16 + gid) * 132;
    const float* xr1 = xr0 + 8 * 132;
    for (int kk = 0; kk < 128; kk += 8) {
        float a0 = xr0[kk + tig],     a1 = xr1[kk + tig];
        float a2 = xr0[kk + tig + 4], a3 = xr1[kk + tig + 4];
        uint32_t ah0 = f2tf32(a0), ah1 = f2tf32(a1), ah2 = f2tf32(a2), ah3 = f2tf32(a3);
        uint32_t al0 = f2tf32(a0 - __uint_as_float(ah0));
        uint32_t al1 = f2tf32(a1 - __uint_as_float(ah1));
        uint32_t al2 = f2tf32(a2 - __uint_as_float(ah2));
        uint32_t al3 = f2tf32(a3 - __uint_as_float(ah3));
        const float* wh0 = Wh + (kk + tig) * 68;
        const float* wh1 = Wh + (kk + tig + 4) * 68;
        const float* wl0 = Wl + (kk + tig) * 68;
        const float* wl1 = Wl + (kk + tig + 4) * 68;
#pragma unroll
        for (int j = 0; j < 8; j++) {
            int n = j * 8 + gid;
            uint32_t bh0 = __float_as_uint(wh0[n]);
            uint32_t bh1 = __float_as_uint(wh1[n]);
            uint32_t bl0 = __float_as_uint(wl0[n]);
            uint32_t bl1 = __float_as_uint(wl1[n]);
            MMA_TF32(acc[j][0], acc[j][1], acc[j][2], acc[j][3],
                     ah0, ah1, ah2, ah3, bh0, bh1);
            MMA_TF32(acc[j][0], acc[j][1], acc[j][2], acc[j][3],
                     al0, al1, al2, al3, bh0, bh1);
            MMA_TF32(acc[j][0], acc[j][1], acc[j][2], acc[j][3],
                     ah0, ah1, ah2, ah3, bl0, bl1);
        }
    }

    int row0 = node0 + wid * 16 + gid;
    int row1 = row0 + 8;
    float s0 = 0.f, s1 = 0.f;
    if (row0 < NN) { s0 = rsqrtf(g_deg[row0]); if (tig == 0) g_dinv[row0] = s0; }
    if (row1 < NN) { s1 = rsqrtf(g_deg[row1]); if (tig == 0) g_dinv[row1] = s1; }
#pragma unroll
    for (int j = 0; j < 8; j++) {
        int col = j * 8 + tig * 2;
        if (row0 < NN) {
            float2 v = make_float2(acc[j][0] * s0, acc[j][1] * s0);
            *(float2*)(g_H1   + (size_t)row0 * 64 + col) = v;
            *(float2*)(g_AGG1 + (size_t)row0 * 64 + col) = v;
        }
        if (row1 < NN) {
            float2 v = make_float2(acc[j][2] * s1, acc[j][3] * s1);
            *(float2*)(g_H1   + (size_t)row1 * 64 + col) = v;
            *(float2*)(g_AGG1 + (size_t)row1 * 64 + col) = v;
        }
    }
}

// ---------------- scatter layer 1: AGG1[dst] += H1s[src], 8 edges per thread ----------------
__global__ __launch_bounds__(256) void k_scatter1() {
    int i = blockIdx.x * 256 + threadIdx.x;
    if (i >= NE * 2) return;             // NE/8 edge-octets x 16 threads
    int e0 = (i >> 4) * 8, c = i & 15;
    unsigned s[8], d[8];
    bool ok[8];
#pragma unroll
    for (int u = 0; u < 8; u++) {
        s[u] = (unsigned)g_src[e0 + u];
        d[u] = (unsigned)g_dst[e0 + u];
        ok[u] = (s[u] < NN) & (d[u] < NN);
    }
    float4 v[8];
#pragma unroll
    for (int u = 0; u < 8; u++)
        if (ok[u]) v[u] = __ldg(((const float4*)g_H1) + s[u] * 16 + c);
#pragma unroll
    for (int u = 0; u < 8; u++)
        if (ok[u]) atomicAdd(((float4*)g_AGG1) + d[u] * 16 + c, v[u]);
}

// ---------------- GEMM2: h = relu(dinv*AGG1 + b1); H2s = (h@W2)*dinv ; out init = H2s ----------------
__global__ __launch_bounds__(256) void k_gemm2(const float* __restrict__ W2,
                                               const float* __restrict__ b1,
                                               float* __restrict__ out) {
    __shared__ float Ws[64 * 32];
    __shared__ float hs[128 * 66];   // pad 2
    const int t = threadIdx.x;
    const int node0 = blockIdx.x * 128;

    for (int i = t; i < 64 * 32; i += 256) Ws[i] = W2[i];
    for (int i = t; i < 128 * 64; i += 256) {
        int row = i >> 6, col = i & 63;
        int node = node0 + row;
        float h = 0.0f;
        if (node < NN) h = fmaxf(fmaf(g_dinv[node], g_AGG1[node * 64 + col], b1[col]), 0.0f);
        hs[row * 66 + col] = h;
    }
    __syncthreads();

    const int ng = t >> 3;   // 4 nodes
    const int cg = t & 7;    // 4 cols
    float acc[4][4];
#pragma unroll
    for (int i = 0; i < 4; i++)
#pragma unroll
        for (int j = 0; j < 4; j++) acc[i][j] = 0.0f;

    const float* hp = hs + ng * 4 * 66;
    const float* wp = Ws + cg * 4;
#pragma unroll 4
    for (int k = 0; k < 64; k++) {
        float4 w = *(const float4*)(wp + k * 32);
        float hv[4];
#pragma unroll
        for (int i = 0; i < 4; i++) hv[i] = hp[i * 66 + k];
#pragma unroll
        for (int i = 0; i < 4; i++) {
            acc[i][0] += hv[i] * w.x; acc[i][1] += hv[i] * w.y;
            acc[i][2] += hv[i] * w.z; acc[i][3] += hv[i] * w.w;
        }
    }

#pragma unroll
    for (int i = 0; i < 4; i++) {
        int node = node0 + ng * 4 + i;
        if (node < NN) {
            float s = g_dinv[node];
            float4 h2 = make_float4(acc[i][0]*s, acc[i][1]*s, acc[i][2]*s, acc[i][3]*s);
            ((float4*)(g_H2 + node * 32 + cg * 4))[0] = h2;
            ((float4*)(out  + node * 32 + cg * 4))[0] = h2;
        }
    }
}

// ---------------- scatter layer 2: out[dst] += H2s[src], 8 edges per thread ----------------
__global__ __launch_bounds__(256) void k_scatter2(float* __restrict__ out) {
    int i = blockIdx.x * 256 + threadIdx.x;
    if (i >= NE) return;                 // NE/8 edge-octets x 8 threads
    int e0 = (i >> 3) * 8, c = i & 7;
    unsigned s[8], d[8];
    bool ok[8];
#pragma unroll
    for (int u = 0; u < 8; u++) {
        s[u] = (unsigned)g_src[e0 + u];
        d[u] = (unsigned)g_dst[e0 + u];
        ok[u] = (s[u] < NN) & (d[u] < NN);
    }
    float4 v[8];
#pragma unroll
    for (int u = 0; u < 8; u++)
        if (ok[u]) v[u] = __ldg(((const float4*)g_H2) + s[u] * 8 + c);
#pragma unroll
    for (int u = 0; u < 8; u++)
        if (ok[u]) atomicAdd(((float4*)out) + d[u] * 8 + c, v[u]);
}

// ---------------- final: out = out * dinv[node] + b2 ----------------
__global__ void k_final(float* __restrict__ out, const float* __restrict__ b2) {
    int i = blockIdx.x * 256 + threadIdx.x;
    if (i >= NN * 8) return;
    int node = i >> 3, cb = (i & 7) * 4;
    float s = g_dinv[node];
    float4 v = ((float4*)out)[i];
    float4 bb = *(const float4*)(b2 + cb);
    ((float4*)out)[i] = make_float4(fmaf(v.x, s, bb.x), fmaf(v.y, s, bb.y),
                                    fmaf(v.z, s, bb.z), fmaf(v.w, s, bb.w));
}

// ---------------- launch ----------------
extern "C" void kernel_launch(void* const* d_in, const int* in_sizes, int n_in,
                              void* d_out, int out_size) {
    const float* x  = (const float*)d_in[0];
    const void*  ei = d_in[1];
    const float* W1 = (const float*)d_in[2];
    const float* b1 = (const float*)d_in[3];
    const float* W2 = (const float*)d_in[4];
    const float* b2 = (const float*)d_in[5];
    float* out = (float*)d_out;

    const int smem1 = (2 * 128 * 68 + 128 * 132) * sizeof(float);  // 137216 B
    cudaFuncSetAttribute(k_gemm1_mma, cudaFuncAttributeMaxDynamicSharedMemorySize, smem1);

    k_init     <<<(NN + 255) / 256, 256>>>((const unsigned*)ei);
    k_prep     <<<(NE / 4 + 255) / 256, 256>>>(ei);
    k_gemm1_mma<<<(NN + 127) / 128, 256, smem1>>>(x, W1);
    k_scatter1 <<<(NE * 2 + 255) / 256, 256>>>();
    k_gemm2    <<<(NN + 127) / 128, 256>>>(W2, b1, out);
    k_scatter2 <<<(NE + 255) / 256, 256>>>(out);
    k_final    <<<(NN * 8 + 255) / 256, 256>>>(out, b2);
}

// round 17
// speedup vs baseline: 1.7939x; 1.0101x over previous
#include <cuda_runtime.h>
#include <cstdint>

#define NN 50000
#define NE 800000
// F_IN=128, F_HID=64, F_OUT=32

// ---------------- scratch (device globals: alloc-free) ----------------
__device__ __align__(16) float g_deg [NN];
__device__ __align__(16) float g_dinv[NN];
__device__ __align__(16) float g_H1  [NN * 64];   // (x@W1) * dinv[node]
__device__ __align__(16) float g_AGG1[NN * 64];
__device__ __align__(16) float g_H2  [NN * 32];   // (h@W2) * dinv[node]
__device__ int g_src[NE];
__device__ int g_dst[NE];
__device__ int g_is64;

__device__ __forceinline__ uint32_t f2tf32(float v) {
    uint32_t r;
    asm("cvt.rna.tf32.f32 %0, %1;" : "=r"(r) : "f"(v));
    return r;
}

#define MMA_TF32(d0,d1,d2,d3,a0,a1,a2,a3,b0,b1) \
    asm volatile("mma.sync.aligned.m16n8k8.row.col.f32.tf32.tf32.f32 " \
                 "{%0,%1,%2,%3}, {%4,%5,%6,%7}, {%8,%9}, {%0,%1,%2,%3};" \
                 : "+f"(d0), "+f"(d1), "+f"(d2), "+f"(d3) \
                 : "r"(a0), "r"(a1), "r"(a2), "r"(a3), "r"(b0), "r"(b1))

// ---------------- init: deg=1 (self-loop) + edge dtype detect ----------------
__global__ void k_init(const unsigned* __restrict__ w) {
    int i = blockIdx.x * 256 + threadIdx.x;
    if (i < NN) g_deg[i] = 1.0f;
    if (blockIdx.x == 0 && threadIdx.x == 0) {
        int all0 = 1;
        for (int k = 0; k < 64; k++)
            if (w[2 * k + 1] != 0u) all0 = 0;
        g_is64 = all0;
    }
}

// decode edge_index to int32 + accumulate degree, 4 edges per thread
__global__ void k_prep(const void* __restrict__ p) {
    int e0 = (blockIdx.x * 256 + threadIdx.x) * 4;
    if (e0 >= NE) return;
    int s[4], d[4];
    if (g_is64) {
        const long long* q = (const long long*)p;
#pragma unroll
        for (int u = 0; u < 4; u++) {
            s[u] = (int)__ldg(q + e0 + u);
            d[u] = (int)__ldg(q + NE + e0 + u);
        }
    } else {
        const int* q = (const int*)p;
#pragma unroll
        for (int u = 0; u < 4; u++) {
            s[u] = __ldg(q + e0 + u);
            d[u] = __ldg(q + NE + e0 + u);
        }
    }
#pragma unroll
    for (int u = 0; u < 4; u++) { g_src[e0 + u] = s[u]; g_dst[e0 + u] = d[u]; }
#pragma unroll
    for (int u = 0; u < 4; u++)
        if ((unsigned)d[u] < NN) atomicAdd(&g_deg[d[u]], 1.0f);
}

// ---------------- GEMM1 (mma.sync tf32, 3xTF32): H1s = (x @ W1) * dinv ; AGG1 = H1s ----------------
// 8 warps; warp owns 16 rows x 64 cols (8 n-tiles of m16n8k8), K=128 in 16 steps.
// W stored with permuted column slot s(n)=(n&7)*8+(n>>3): thread's 8 B-values (j=0..7)
// are contiguous -> 2x LDS.128 per fragment row instead of 8x LDS.32.
__global__ __launch_bounds__(256) void k_gemm1_mma(const float* __restrict__ x,
                                                   const float* __restrict__ W1) {
    extern __shared__ float sm[];
    float* Wh = sm;                   // [128][68] tf32-hi, permuted cols
    float* Wl = sm + 128 * 68;        // [128][68] tf32-lo, permuted cols
    float* xs = sm + 2 * 128 * 68;    // [128][132] fp32 x tile
    const int t = threadIdx.x, wid = t >> 5, lane = t & 31;
    const int gid = lane >> 2, tig = lane & 3;   // groupID, threadID-in-group
    const int node0 = blockIdx.x * 128;

    for (int i = t; i < 128 * 64; i += 256) {
        int k = i >> 6, n = i & 63;
        int slot = ((n & 7) << 3) | (n >> 3);    // permuted column
        float w = W1[i];
        uint32_t hb = f2tf32(w);
        float hf = __uint_as_float(hb);
        Wh[k * 68 + slot] = hf;
        Wl[k * 68 + slot] = __uint_as_float(f2tf32(w - hf));
    }
    for (int i4 = t; i4 < 128 * 32; i4 += 256) {
        int row = i4 >> 5, q = i4 & 31;
        int node = node0 + row;
        float4 v = make_float4(0.f, 0.f, 0.f, 0.f);
        if (node < NN) v = ((const float4*)(x + (size_t)node * 128))[q];
        *(float4*)(xs + row * 132 + q * 4) = v;
    }
    __syncthreads();

    float acc[8][4];
#pragma unroll
    for (int j = 0; j < 8; j++)
#pragma unroll
        for (int c = 0; c < 4; c++) acc[j][c] = 0.0f;

    const float* xr0 = xs + (wid * 16 + gid) * 132;
    const float* xr1 = xr0 + 8 * 132;
    for (int kk = 0; kk < 128; kk += 8) {
        // A fragment, hi/lo split in regs
        float a0 = xr0[kk + tig],     a1 = xr1[kk + tig];
        float a2 = xr0[kk + tig + 4], a3 = xr1[kk + tig + 4];
        uint32_t ah0 = f2tf32(a0), ah1 = f2tf32(a1), ah2 = f2tf32(a2), ah3 = f2tf32(a3);
        uint32_t al0 = f2tf32(a0 - __uint_as_float(ah0));
        uint32_t al1 = f2tf32(a1 - __uint_as_float(ah1));
        uint32_t al2 = f2tf32(a2 - __uint_as_float(ah2));
        uint32_t al3 = f2tf32(a3 - __uint_as_float(ah3));
        // B fragments: vectorized from permuted layout
        float bh0v[8], bh1v[8], bl0v[8], bl1v[8];
        {
            const float* r0 = Wh + (kk + tig) * 68 + gid * 8;
            const float* r1 = Wh + (kk + tig + 4) * 68 + gid * 8;
            const float* r2 = Wl + (kk + tig) * 68 + gid * 8;
            const float* r3 = Wl + (kk + tig + 4) * 68 + gid * 8;
            *(float4*)(bh0v)     = *(const float4*)(r0);
            *(float4*)(bh0v + 4) = *(const float4*)(r0 + 4);
            *(float4*)(bh1v)     = *(const float4*)(r1);
            *(float4*)(bh1v + 4) = *(const float4*)(r1 + 4);
            *(float4*)(bl0v)     = *(const float4*)(r2);
            *(float4*)(bl0v + 4) = *(const float4*)(r2 + 4);
            *(float4*)(bl1v)     = *(const float4*)(r3);
            *(float4*)(bl1v + 4) = *(const float4*)(r3 + 4);
        }
#pragma unroll
        for (int j = 0; j < 8; j++) {
            uint32_t bh0 = __float_as_uint(bh0v[j]);
            uint32_t bh1 = __float_as_uint(bh1v[j]);
            uint32_t bl0 = __float_as_uint(bl0v[j]);
            uint32_t bl1 = __float_as_uint(bl1v[j]);
            MMA_TF32(acc[j][0], acc[j][1], acc[j][2], acc[j][3],
                     ah0, ah1, ah2, ah3, bh0, bh1);
            MMA_TF32(acc[j][0], acc[j][1], acc[j][2], acc[j][3],
                     al0, al1, al2, al3, bh0, bh1);
            MMA_TF32(acc[j][0], acc[j][1], acc[j][2], acc[j][3],
                     ah0, ah1, ah2, ah3, bl0, bl1);
        }
    }

    // epilogue (mapping unchanged: acc[j] -> col j*8 + tig*2)
    int row0 = node0 + wid * 16 + gid;
    int row1 = row0 + 8;
    float s0 = 0.f, s1 = 0.f;
    if (row0 < NN) { s0 = rsqrtf(g_deg[row0]); if (tig == 0) g_dinv[row0] = s0; }
    if (row1 < NN) { s1 = rsqrtf(g_deg[row1]); if (tig == 0) g_dinv[row1] = s1; }
#pragma unroll
    for (int j = 0; j < 8; j++) {
        int col = j * 8 + tig * 2;
        if (row0 < NN) {
            float2 v = make_float2(acc[j][0] * s0, acc[j][1] * s0);
            *(float2*)(g_H1   + (size_t)row0 * 64 + col) = v;
            *(float2*)(g_AGG1 + (size_t)row0 * 64 + col) = v;
        }
        if (row1 < NN) {
            float2 v = make_float2(acc[j][2] * s1, acc[j][3] * s1);
            *(float2*)(g_H1   + (size_t)row1 * 64 + col) = v;
            *(float2*)(g_AGG1 + (size_t)row1 * 64 + col) = v;
        }
    }
}

// ---------------- scatter layer 1: AGG1[dst] += H1s[src], 4 edges per thread ----------------
__global__ __launch_bounds__(256) void k_scatter1() {
    int i = blockIdx.x * 256 + threadIdx.x;
    if (i >= NE * 4) return;             // NE/4 edge-quads x 16 threads
    int e0 = (i >> 4) * 4, c = i & 15;
    unsigned s[4], d[4];
    bool ok[4];
#pragma unroll
    for (int u = 0; u < 4; u++) {
        s[u] = (unsigned)g_src[e0 + u];
        d[u] = (unsigned)g_dst[e0 + u];
        ok[u] = (s[u] < NN) & (d[u] < NN);
    }
    float4 v[4];
#pragma unroll
    for (int u = 0; u < 4; u++)
        if (ok[u]) v[u] = __ldg(((const float4*)g_H1) + s[u] * 16 + c);
#pragma unroll
    for (int u = 0; u < 4; u++)
        if (ok[u]) atomicAdd(((float4*)g_AGG1) + d[u] * 16 + c, v[u]);
}

// ---------------- GEMM2: h = relu(dinv*AGG1 + b1); H2s = (h@W2)*dinv ; out init = H2s ----------------
__global__ __launch_bounds__(256) void k_gemm2(const float* __restrict__ W2,
                                               const float* __restrict__ b1,
                                               float* __restrict__ out) {
    __shared__ float Ws[64 * 32];
    __shared__ float hs[128 * 66];   // pad 2
    const int t = threadIdx.x;
    const int node0 = blockIdx.x * 128;

    for (int i = t; i < 64 * 32; i += 256) Ws[i] = W2[i];
    for (int i = t; i < 128 * 64; i += 256) {
        int row = i >> 6, col = i & 63;
        int node = node0 + row;
        float h = 0.0f;
        if (node < NN) h = fmaxf(fmaf(g_dinv[node], g_AGG1[node * 64 + col], b1[col]), 0.0f);
        hs[row * 66 + col] = h;
    }
    __syncthreads();

    const int ng = t >> 3;   // 4 nodes
    const int cg = t & 7;    // 4 cols
    float acc[4][4];
#pragma unroll
    for (int i = 0; i < 4; i++)
#pragma unroll
        for (int j = 0; j < 4; j++) acc[i][j] = 0.0f;

    const float* hp = hs + ng * 4 * 66;
    const float* wp = Ws + cg * 4;
#pragma unroll 4
    for (int k = 0; k < 64; k++) {
        float4 w = *(const float4*)(wp + k * 32);
        float hv[4];
#pragma unroll
        for (int i = 0; i < 4; i++) hv[i] = hp[i * 66 + k];
#pragma unroll
        for (int i = 0; i < 4; i++) {
            acc[i][0] += hv[i] * w.x; acc[i][1] += hv[i] * w.y;
            acc[i][2] += hv[i] * w.z; acc[i][3] += hv[i] * w.w;
        }
    }

#pragma unroll
    for (int i = 0; i < 4; i++) {
        int node = node0 + ng * 4 + i;
        if (node < NN) {
            float s = g_dinv[node];
            float4 h2 = make_float4(acc[i][0]*s, acc[i][1]*s, acc[i][2]*s, acc[i][3]*s);
            ((float4*)(g_H2 + node * 32 + cg * 4))[0] = h2;
            ((float4*)(out  + node * 32 + cg * 4))[0] = h2;
        }
    }
}

// ---------------- scatter layer 2: out[dst] += H2s[src], 4 edges per thread ----------------
__global__ __launch_bounds__(256) void k_scatter2(float* __restrict__ out) {
    int i = blockIdx.x * 256 + threadIdx.x;
    if (i >= NE * 2) return;             // NE/4 edge-quads x 8 threads
    int e0 = (i >> 3) * 4, c = i & 7;
    unsigned s[4], d[4];
    bool ok[4];
#pragma unroll
    for (int u = 0; u < 4; u++) {
        s[u] = (unsigned)g_src[e0 + u];
        d[u] = (unsigned)g_dst[e0 + u];
        ok[u] = (s[u] < NN) & (d[u] < NN);
    }
    float4 v[4];
#pragma unroll
    for (int u = 0; u < 4; u++)
        if (ok[u]) v[u] = __ldg(((const float4*)g_H2) + s[u] * 8 + c);
#pragma unroll
    for (int u = 0; u < 4; u++)
        if (ok[u]) atomicAdd(((float4*)out) + d[u] * 8 + c, v[u]);
}

// ---------------- final: out = out * dinv[node] + b2 ----------------
__global__ void k_final(float* __restrict__ out, const float* __restrict__ b2) {
    int i = blockIdx.x * 256 + threadIdx.x;
    if (i >= NN * 8) return;
    int node = i >> 3, cb = (i & 7) * 4;
    float s = g_dinv[node];
    float4 v = ((float4*)out)[i];
    float4 bb = *(const float4*)(b2 + cb);
    ((float4*)out)[i] = make_float4(fmaf(v.x, s, bb.x), fmaf(v.y, s, bb.y),
                                    fmaf(v.z, s, bb.z), fmaf(v.w, s, bb.w));
}

// ---------------- launch ----------------
extern "C" void kernel_launch(void* const* d_in, const int* in_sizes, int n_in,
                              void* d_out, int out_size) {
    const float* x  = (const float*)d_in[0];
    const void*  ei = d_in[1];
    const float* W1 = (const float*)d_in[2];
    const float* b1 = (const float*)d_in[3];
    const float* W2 = (const float*)d_in[4];
    const float* b2 = (const float*)d_in[5];
    float* out = (float*)d_out;

    const int smem1 = (2 * 128 * 68 + 128 * 132) * sizeof(float);  // 137216 B
    cudaFuncSetAttribute(k_gemm1_mma, cudaFuncAttributeMaxDynamicSharedMemorySize, smem1);

    k_init     <<<(NN + 255) / 256, 256>>>((const unsigned*)ei);
    k_prep     <<<(NE / 4 + 255) / 256, 256>>>(ei);
    k_gemm1_mma<<<(NN + 127) / 128, 256, smem1>>>(x, W1);
    k_scatter1 <<<(NE * 4 + 255) / 256, 256>>>();
    k_gemm2    <<<(NN + 127) / 128, 256>>>(W2, b1, out);
    k_scatter2 <<<(NE * 2 + 255) / 256, 256>>>(out);
    k_final    <<<(NN * 8 + 255) / 256, 256>>>(out, b2);
}